// round 1
// baseline (speedup 1.0000x reference)
#include <cuda_runtime.h>
#include <cuda_bf16.h>
#include <math.h>

// Problem constants (fixed by the reference)
constexpr int NN  = 100000;   // target nodes
constexpr int NN1 = 60000;    // nei1 nodes
constexpr int NN2 = 30000;    // nei2 nodes
constexpr int EE  = 1600000;  // edges per relation
constexpr int DIN = 128;
constexpr int HH  = 64;

// ---------------- scratch (device global, no allocation) ----------------
// layout (floats):
//  hmask  : NN*HH        = 6,400,000
//  hnei1  : NN1*HH       = 3,840,000
//  hnei2  : NN2*HH       = 1,920,000
//  sum1   : NN*HH        = 6,400,000
//  sum2   : NN*HH        = 6,400,000
//  T1     : NN*HH        = 6,400,000
//  T2     : NN*HH        = 6,400,000
//  cnt1   : NN           =   100,000
//  cnt2   : NN           =   100,000
constexpr long long OFF_HMASK = 0;
constexpr long long OFF_HNEI1 = OFF_HMASK + (long long)NN * HH;
constexpr long long OFF_HNEI2 = OFF_HNEI1 + (long long)NN1 * HH;
constexpr long long OFF_SUM1  = OFF_HNEI2 + (long long)NN2 * HH;
constexpr long long OFF_SUM2  = OFF_SUM1 + (long long)NN * HH;
constexpr long long OFF_T1    = OFF_SUM2 + (long long)NN * HH;
constexpr long long OFF_T2    = OFF_T1 + (long long)NN * HH;
constexpr long long OFF_CNT1  = OFF_T2 + (long long)NN * HH;
constexpr long long OFF_CNT2  = OFF_CNT1 + NN;
constexpr long long SCRATCH_TOTAL = OFF_CNT2 + NN;

__device__ float g_scratch[SCRATCH_TOTAL];

// ---------------- helpers ----------------
__device__ __forceinline__ float elu1(float x) { return x > 0.f ? x : expm1f(x); }

__device__ __forceinline__ float4 elu4(float4 v) {
    v.x = elu1(v.x); v.y = elu1(v.y); v.z = elu1(v.z); v.w = elu1(v.w);
    return v;
}

// ---------------- GEMM + optional bias/ELU ----------------
// Y[r, c] = (elu)( sum_k X[r,k] * W[k,c] + b[c] ),  c in [0,64)
// W transposed into smem with +4 float pad so float4 reads over k are
// conflict-free per quarter-warp (stride mod 32 == 4).
template<int K, int BM, bool BIASELU>
__global__ __launch_bounds__(256)
void gemm_elu_kernel(const float* __restrict__ X, const float* __restrict__ W,
                     const float* __restrict__ b, float* __restrict__ Y, int rows)
{
    constexpr int WS = K + 4;
    __shared__ float Wt[64 * WS];
    __shared__ float Xs[BM * K];

    const int t = threadIdx.x;

    // Load W [K,64] -> Wt[c][k] transposed
    for (int idx = t; idx < K * 64; idx += 256) {
        int k = idx >> 6, c = idx & 63;
        Wt[c * WS + k] = W[idx];
    }

    const int rowBase = blockIdx.x * BM;

    // Load X tile as float4, zero-pad out-of-range rows
    constexpr int NV = BM * K / 4;
    const float4* X4 = (const float4*)X;
    float4* Xs4 = (float4*)Xs;
    for (int idx = t; idx < NV; idx += 256) {
        int r = idx / (K / 4);
        int gr = rowBase + r;
        float4 v = make_float4(0.f, 0.f, 0.f, 0.f);
        if (gr < rows) v = X4[(long long)gr * (K / 4) + (idx % (K / 4))];
        Xs4[idx] = v;
    }
    __syncthreads();

    const int c  = t & 63;
    const int rg = t >> 6;          // 0..3
    constexpr int RPT = BM / 4;     // rows per thread

    float acc[RPT];
#pragma unroll
    for (int r = 0; r < RPT; r++) acc[r] = 0.f;

    const float4* wrow = (const float4*)&Wt[c * WS];
#pragma unroll
    for (int k4 = 0; k4 < K / 4; k4++) {
        float4 wv = wrow[k4];
#pragma unroll
        for (int r = 0; r < RPT; r++) {
            float4 xv = ((const float4*)&Xs[(rg * RPT + r) * K])[k4];
            acc[r] += wv.x * xv.x + wv.y * xv.y + wv.z * xv.z + wv.w * xv.w;
        }
    }

    float bias = 0.f;
    if (BIASELU) bias = b[c];
#pragma unroll
    for (int r = 0; r < RPT; r++) {
        int gr = rowBase + rg * RPT + r;
        if (gr < rows) {
            float v = acc[r] + bias;
            if (BIASELU) v = elu1(v);
            Y[(long long)gr * 64 + c] = v;
        }
    }
}

// ---------------- zero accumulators ----------------
__global__ __launch_bounds__(256)
void zero_kernel(float4* __restrict__ s1, float4* __restrict__ s2,
                 float* __restrict__ c1, float* __restrict__ c2)
{
    int i = blockIdx.x * 256 + threadIdx.x;   // [0, NN*16)
    if (i < NN * 16) {
        float4 z = make_float4(0.f, 0.f, 0.f, 0.f);
        s1[i] = z;
        s2[i] = z;
    }
    if (i < NN) { c1[i] = 0.f; c2[i] = 0.f; }
}

// ---------------- edge scatter: sum[src] += hnei[dst]; cnt[src] += 1 ----------------
// 16 threads per edge; each handles one 16B chunk of the 64-float row.
__global__ __launch_bounds__(256)
void scatter_kernel(const int* __restrict__ src, const int* __restrict__ dst,
                    const float* __restrict__ hnei, float* __restrict__ sum,
                    float* __restrict__ cnt, int E)
{
    int gid = blockIdx.x * 256 + threadIdx.x;
    int e = gid >> 4;
    if (e >= E) return;
    int c = gid & 15;
    int s = __ldg(src + e);
    int d = __ldg(dst + e);
    float4 v = __ldg((const float4*)hnei + (long long)d * 16 + c);
    float* p = sum + (long long)s * 64 + c * 4;
    asm volatile("red.global.add.v4.f32 [%0], {%1,%2,%3,%4};"
                 :: "l"(p), "f"(v.x), "f"(v.y), "f"(v.z), "f"(v.w) : "memory");
    if (c == 0) atomicAdd(cnt + s, 1.0f);
}

// ---------------- final fused epilogue ----------------
// agg_r = T_r[i] / max(cnt_r[i], 1)
// out0 = elu(htar + agg1); out1 = elu(hmask + agg1)
// out2 = elu(htar + agg2); out3 = elu(hmask + agg2); out4 = htar (already written)
__global__ __launch_bounds__(256)
void final_kernel(const float4* __restrict__ T1, const float4* __restrict__ T2,
                  const float* __restrict__ cnt1, const float* __restrict__ cnt2,
                  const float4* __restrict__ hmask, float* __restrict__ out)
{
    int g = blockIdx.x * 256 + threadIdx.x;   // [0, NN*16)
    if (g >= NN * 16) return;
    int i = g >> 4;

    float c1 = cnt1[i];
    float c2 = cnt2[i];
    float inv1 = c1 > 0.f ? 1.f / c1 : 1.f;
    float inv2 = c2 > 0.f ? 1.f / c2 : 1.f;

    float4 a1 = T1[g];
    a1.x *= inv1; a1.y *= inv1; a1.z *= inv1; a1.w *= inv1;
    float4 a2 = T2[g];
    a2.x *= inv2; a2.y *= inv2; a2.z *= inv2; a2.w *= inv2;

    const float4* HT = (const float4*)(out + 4LL * NN * HH);
    float4 ht = HT[g];
    float4 hm = hmask[g];

    float4 v;
    v = make_float4(ht.x + a1.x, ht.y + a1.y, ht.z + a1.z, ht.w + a1.w);
    ((float4*)(out + 0LL * NN * HH))[g] = elu4(v);
    v = make_float4(hm.x + a1.x, hm.y + a1.y, hm.z + a1.z, hm.w + a1.w);
    ((float4*)(out + 1LL * NN * HH))[g] = elu4(v);
    v = make_float4(ht.x + a2.x, ht.y + a2.y, ht.z + a2.z, ht.w + a2.w);
    ((float4*)(out + 2LL * NN * HH))[g] = elu4(v);
    v = make_float4(hm.x + a2.x, hm.y + a2.y, hm.z + a2.z, hm.w + a2.w);
    ((float4*)(out + 3LL * NN * HH))[g] = elu4(v);
}

// ---------------- launch ----------------
extern "C" void kernel_launch(void* const* d_in, const int* in_sizes, int n_in,
                              void* d_out, int out_size)
{
    const float* feats0    = (const float*)d_in[0];
    const float* feats1    = (const float*)d_in[1];
    const float* feats2    = (const float*)d_in[2];
    const float* mask_feat = (const float*)d_in[3];
    const int*   src1      = (const int*)d_in[4];
    const int*   dst1      = (const int*)d_in[5];
    const int*   src2      = (const int*)d_in[6];
    const int*   dst2      = (const int*)d_in[7];
    const float* W0        = (const float*)d_in[8];
    const float* b0        = (const float*)d_in[9];
    const float* W1        = (const float*)d_in[10];
    const float* b1        = (const float*)d_in[11];
    const float* W2        = (const float*)d_in[12];
    const float* b2        = (const float*)d_in[13];
    const float* A0        = (const float*)d_in[14];
    const float* A1        = (const float*)d_in[15];

    float* out = (float*)d_out;

    void* sp = nullptr;
    cudaGetSymbolAddress(&sp, g_scratch);
    float* S = (float*)sp;
    float* hmask = S + OFF_HMASK;
    float* hnei1 = S + OFF_HNEI1;
    float* hnei2 = S + OFF_HNEI2;
    float* sum1  = S + OFF_SUM1;
    float* sum2  = S + OFF_SUM2;
    float* T1    = S + OFF_T1;
    float* T2    = S + OFF_T2;
    float* cnt1  = S + OFF_CNT1;
    float* cnt2  = S + OFF_CNT2;

    float* htar = out + 4LL * NN * HH;   // slot 4 of the output stack

    constexpr int BM = 24;
    auto cdiv = [](int a, int b) { return (a + b - 1) / b; };

    // 1. zero accumulators
    zero_kernel<<<cdiv(NN * 16, 256), 256>>>((float4*)sum1, (float4*)sum2, cnt1, cnt2);

    // 2. input GEMMs (+bias +ELU)
    gemm_elu_kernel<DIN, BM, true><<<cdiv(NN,  BM), 256>>>(feats0,    W0, b0, htar,  NN);
    gemm_elu_kernel<DIN, BM, true><<<cdiv(NN,  BM), 256>>>(mask_feat, W0, b0, hmask, NN);
    gemm_elu_kernel<DIN, BM, true><<<cdiv(NN1, BM), 256>>>(feats1,    W1, b1, hnei1, NN1);
    gemm_elu_kernel<DIN, BM, true><<<cdiv(NN2, BM), 256>>>(feats2,    W2, b2, hnei2, NN2);

    // 3. edge aggregation (segment-sum by src + degree count)
    scatter_kernel<<<cdiv(EE * 16, 256), 256>>>(src1, dst1, hnei1, sum1, cnt1, EE);
    scatter_kernel<<<cdiv(EE * 16, 256), 256>>>(src2, dst2, hnei2, sum2, cnt2, EE);

    // 4. T_r = sum_r @ A_r (division by cnt deferred — commutes with matmul)
    gemm_elu_kernel<HH, BM, false><<<cdiv(NN, BM), 256>>>(sum1, A0, nullptr, T1, NN);
    gemm_elu_kernel<HH, BM, false><<<cdiv(NN, BM), 256>>>(sum2, A1, nullptr, T2, NN);

    // 5. fused epilogue
    final_kernel<<<cdiv(NN * 16, 256), 256>>>((const float4*)T1, (const float4*)T2,
                                              cnt1, cnt2, (const float4*)hmask, out);
}

// round 3
// speedup vs baseline: 1.2413x; 1.2413x over previous
#include <cuda_runtime.h>
#include <math.h>

// Problem constants (fixed by the reference)
constexpr int NN  = 100000;
constexpr int NN1 = 60000;
constexpr int NN2 = 30000;
constexpr int EE  = 1600000;
constexpr int DIN = 128;
constexpr int HH  = 64;

// ---------------- float scratch ----------------
constexpr long long F_HMASK = 0;
constexpr long long F_HNEI1 = F_HMASK + (long long)NN * HH;
constexpr long long F_HNEI2 = F_HNEI1 + (long long)NN1 * HH;
constexpr long long F_SUM1  = F_HNEI2 + (long long)NN2 * HH;
constexpr long long F_SUM2  = F_SUM1 + (long long)NN * HH;
constexpr long long F_T1    = F_SUM2 + (long long)NN * HH;
constexpr long long F_T2    = F_T1 + (long long)NN * HH;
constexpr long long F_TOTAL = F_T2 + (long long)NN * HH;

__device__ float g_fscratch[F_TOTAL];

// ---------------- int scratch ----------------
constexpr long long I_DEG1 = 0;
constexpr long long I_DEG2 = I_DEG1 + NN;
constexpr long long I_ROW1 = I_DEG2 + NN;
constexpr long long I_ROW2 = I_ROW1 + NN;
constexpr long long I_CUR1 = I_ROW2 + NN;
constexpr long long I_CUR2 = I_CUR1 + NN;
constexpr long long I_CTR  = I_CUR2 + NN;     // 2 counters, pad to 32
constexpr long long I_EDST1 = I_CTR + 32;
constexpr long long I_EDST2 = I_EDST1 + EE;
constexpr long long I_TOTAL = I_EDST2 + EE;

__device__ int g_iscratch[I_TOTAL];

// ---------------- helpers ----------------
__device__ __forceinline__ float elu1(float x) { return x > 0.f ? x : expm1f(x); }
__device__ __forceinline__ float4 elu4(float4 v) {
    v.x = elu1(v.x); v.y = elu1(v.y); v.z = elu1(v.z); v.w = elu1(v.w);
    return v;
}

// ---------------- GEMM: Y[r,c] = (elu)(X[r,:K] @ W[:K,64] + b) ----------------
// 64x64 tile, 256 threads, each thread computes a 4x4 register block.
// Xs row-major [64][K4] float4 (xv loads are broadcast within 16-lane groups).
// Wt transposed [64 cols][K4] float4 with XOR swizzle (k4 ^ (c4&7)) so the 16
// distinct wv column loads per warp are bank-conflict-free.
template<int K, bool BIASELU>
__global__ __launch_bounds__(256)
void gemm64_kernel(const float* __restrict__ X, const float* __restrict__ W,
                   const float* __restrict__ b, float* __restrict__ Y, int rows)
{
    constexpr int K4 = K / 4;
    __shared__ float4 Xs[64 * K4];
    __shared__ float4 Wt[64 * K4];

    const int t = threadIdx.x;
    const int rowBase = blockIdx.x * 64;

    // Load X tile: idx = r*K4 + k4, lanes consecutive in k4 -> coalesced
    const float4* X4 = (const float4*)X;
    for (int idx = t; idx < 64 * K4; idx += 256) {
        int r  = idx / K4;
        int k4 = idx % K4;
        int gr = rowBase + r;
        float4 v = make_float4(0.f, 0.f, 0.f, 0.f);
        if (gr < rows) v = X4[(long long)gr * K4 + k4];
        Xs[idx] = v;
    }
    // Load W [K][64] transposed into Wt[c][k4 ^ ((c>>2)&7)]
    for (int idx = t; idx < K * 64; idx += 256) {
        int k = idx >> 6;
        int c = idx & 63;
        int k4 = k >> 2, kk = k & 3;
        ((float*)&Wt[c * K4 + (k4 ^ ((c >> 2) & 7))])[kk] = W[idx];
    }
    __syncthreads();

    const int c4  = t & 15;          // float4 column index (cols c4*4..c4*4+3)
    const int r0  = (t >> 4) * 4;    // first row of this thread's block
    const int swz = c4 & 7;

    float acc[4][4];
#pragma unroll
    for (int i = 0; i < 4; i++)
#pragma unroll
        for (int j = 0; j < 4; j++) acc[i][j] = 0.f;

#pragma unroll 8
    for (int k4 = 0; k4 < K4; k4++) {
        float4 xv[4], wv[4];
#pragma unroll
        for (int i = 0; i < 4; i++) xv[i] = Xs[(r0 + i) * K4 + k4];
#pragma unroll
        for (int j = 0; j < 4; j++) wv[j] = Wt[(c4 * 4 + j) * K4 + (k4 ^ swz)];
#pragma unroll
        for (int i = 0; i < 4; i++)
#pragma unroll
            for (int j = 0; j < 4; j++)
                acc[i][j] += xv[i].x * wv[j].x + xv[i].y * wv[j].y +
                             xv[i].z * wv[j].z + xv[i].w * wv[j].w;
    }

    float4 bias = make_float4(0.f, 0.f, 0.f, 0.f);
    if (BIASELU) bias = ((const float4*)b)[c4];

    float4* Y4 = (float4*)Y;
#pragma unroll
    for (int i = 0; i < 4; i++) {
        int gr = rowBase + r0 + i;
        if (gr < rows) {
            float4 o = make_float4(acc[i][0] + bias.x, acc[i][1] + bias.y,
                                   acc[i][2] + bias.z, acc[i][3] + bias.w);
            if (BIASELU) o = elu4(o);
            Y4[(long long)gr * 16 + c4] = o;
        }
    }
}

// ---------------- zero: deg arrays + counters ----------------
__global__ __launch_bounds__(256)
void zero_kernel(int* __restrict__ d1, int* __restrict__ d2, int* __restrict__ ctr)
{
    int i = blockIdx.x * 256 + threadIdx.x;
    if (i < NN) { d1[i] = 0; d2[i] = 0; }
    if (i < 2) ctr[i] = 0;
}

// ---------------- histogram: deg[src[e]]++ ----------------
__global__ __launch_bounds__(256)
void hist_kernel(const int* __restrict__ src, int* __restrict__ deg, int E)
{
    int e = blockIdx.x * 256 + threadIdx.x;
    if (e < E) atomicAdd(deg + __ldg(src + e), 1);
}

// ---------------- base assignment: rowptr/cursor via block-aggregated scan ----------------
__global__ __launch_bounds__(256)
void base_kernel(const int* __restrict__ deg, int* __restrict__ rowptr,
                 int* __restrict__ cursor, int* __restrict__ counter, int n)
{
    __shared__ int warpTot[8];
    __shared__ int blockBase;
    int i = blockIdx.x * 256 + threadIdx.x;
    int lane = threadIdx.x & 31;
    int wid  = threadIdx.x >> 5;

    int d = (i < n) ? deg[i] : 0;
    int x = d;
#pragma unroll
    for (int o = 1; o < 32; o <<= 1) {
        int y = __shfl_up_sync(0xffffffffu, x, o);
        if (lane >= o) x += y;
    }
    if (lane == 31) warpTot[wid] = x;
    __syncthreads();
    if (threadIdx.x == 0) {
        int s = 0;
#pragma unroll
        for (int w = 0; w < 8; w++) { int tw = warpTot[w]; warpTot[w] = s; s += tw; }
        blockBase = atomicAdd(counter, s);
    }
    __syncthreads();
    int base = blockBase + warpTot[wid] + x - d;
    if (i < n) { rowptr[i] = base; cursor[i] = base; }
}

// ---------------- reorder: edst[pos] = dst[e], pos = cursor[src[e]]++ ----------------
__global__ __launch_bounds__(256)
void reorder_kernel(const int* __restrict__ src, const int* __restrict__ dst,
                    int* __restrict__ cursor, int* __restrict__ edst, int E)
{
    int e = blockIdx.x * 256 + threadIdx.x;
    if (e >= E) return;
    int s = __ldg(src + e);
    int pos = atomicAdd(cursor + s, 1);
    edst[pos] = __ldg(dst + e);
}

// ---------------- aggregate: one warp per node, gather rows, write sum once ----------------
__global__ __launch_bounds__(256)
void agg_kernel(const int* __restrict__ rowptr, const int* __restrict__ deg,
                const int* __restrict__ edst, const float2* __restrict__ hnei,
                float2* __restrict__ sum, int n)
{
    int warp = (blockIdx.x * 256 + threadIdx.x) >> 5;
    int lane = threadIdx.x & 31;
    if (warp >= n) return;

    int base = __ldg(rowptr + warp);
    int d    = __ldg(deg + warp);

    float2 acc = make_float2(0.f, 0.f);
    for (int j0 = 0; j0 < d; j0 += 32) {
        int e = 0;
        if (j0 + lane < d) e = __ldg(edst + base + j0 + lane);
        int m = min(32, d - j0);
        int jj = 0;
        for (; jj + 4 <= m; jj += 4) {
            int d0 = __shfl_sync(0xffffffffu, e, jj);
            int d1 = __shfl_sync(0xffffffffu, e, jj + 1);
            int d2 = __shfl_sync(0xffffffffu, e, jj + 2);
            int d3 = __shfl_sync(0xffffffffu, e, jj + 3);
            float2 v0 = __ldg(hnei + (long long)d0 * 32 + lane);
            float2 v1 = __ldg(hnei + (long long)d1 * 32 + lane);
            float2 v2 = __ldg(hnei + (long long)d2 * 32 + lane);
            float2 v3 = __ldg(hnei + (long long)d3 * 32 + lane);
            acc.x += v0.x + v1.x + v2.x + v3.x;
            acc.y += v0.y + v1.y + v2.y + v3.y;
        }
        for (; jj < m; jj++) {
            int dd = __shfl_sync(0xffffffffu, e, jj);
            float2 v = __ldg(hnei + (long long)dd * 32 + lane);
            acc.x += v.x;
            acc.y += v.y;
        }
    }
    sum[(long long)warp * 32 + lane] = acc;
}

// ---------------- final fused epilogue ----------------
__global__ __launch_bounds__(256)
void final_kernel(const float4* __restrict__ T1, const float4* __restrict__ T2,
                  const int* __restrict__ deg1, const int* __restrict__ deg2,
                  const float4* __restrict__ hmask, float* __restrict__ out)
{
    int g = blockIdx.x * 256 + threadIdx.x;   // [0, NN*16)
    if (g >= NN * 16) return;
    int i = g >> 4;

    int c1 = deg1[i];
    int c2 = deg2[i];
    float inv1 = c1 > 0 ? 1.f / (float)c1 : 1.f;
    float inv2 = c2 > 0 ? 1.f / (float)c2 : 1.f;

    float4 a1 = T1[g];
    a1.x *= inv1; a1.y *= inv1; a1.z *= inv1; a1.w *= inv1;
    float4 a2 = T2[g];
    a2.x *= inv2; a2.y *= inv2; a2.z *= inv2; a2.w *= inv2;

    const float4* HT = (const float4*)(out + 4LL * NN * HH);
    float4 ht = HT[g];
    float4 hm = hmask[g];

    float4 v;
    v = make_float4(ht.x + a1.x, ht.y + a1.y, ht.z + a1.z, ht.w + a1.w);
    ((float4*)(out + 0LL * NN * HH))[g] = elu4(v);
    v = make_float4(hm.x + a1.x, hm.y + a1.y, hm.z + a1.z, hm.w + a1.w);
    ((float4*)(out + 1LL * NN * HH))[g] = elu4(v);
    v = make_float4(ht.x + a2.x, ht.y + a2.y, ht.z + a2.z, ht.w + a2.w);
    ((float4*)(out + 2LL * NN * HH))[g] = elu4(v);
    v = make_float4(hm.x + a2.x, hm.y + a2.y, hm.z + a2.z, hm.w + a2.w);
    ((float4*)(out + 3LL * NN * HH))[g] = elu4(v);
}

// ---------------- launch ----------------
extern "C" void kernel_launch(void* const* d_in, const int* in_sizes, int n_in,
                              void* d_out, int out_size)
{
    const float* feats0    = (const float*)d_in[0];
    const float* feats1    = (const float*)d_in[1];
    const float* feats2    = (const float*)d_in[2];
    const float* mask_feat = (const float*)d_in[3];
    const int*   src1      = (const int*)d_in[4];
    const int*   dst1      = (const int*)d_in[5];
    const int*   src2      = (const int*)d_in[6];
    const int*   dst2      = (const int*)d_in[7];
    const float* W0        = (const float*)d_in[8];
    const float* b0        = (const float*)d_in[9];
    const float* W1        = (const float*)d_in[10];
    const float* b1        = (const float*)d_in[11];
    const float* W2        = (const float*)d_in[12];
    const float* b2        = (const float*)d_in[13];
    const float* A0        = (const float*)d_in[14];
    const float* A1        = (const float*)d_in[15];

    float* out = (float*)d_out;

    void* fp = nullptr; cudaGetSymbolAddress(&fp, g_fscratch);
    void* ip = nullptr; cudaGetSymbolAddress(&ip, g_iscratch);
    float* F = (float*)fp;
    int*   I = (int*)ip;

    float* hmask = F + F_HMASK;
    float* hnei1 = F + F_HNEI1;
    float* hnei2 = F + F_HNEI2;
    float* sum1  = F + F_SUM1;
    float* sum2  = F + F_SUM2;
    float* T1    = F + F_T1;
    float* T2    = F + F_T2;

    int* deg1 = I + I_DEG1;
    int* deg2 = I + I_DEG2;
    int* row1 = I + I_ROW1;
    int* row2 = I + I_ROW2;
    int* cur1 = I + I_CUR1;
    int* cur2 = I + I_CUR2;
    int* ctr  = I + I_CTR;
    int* edst1 = I + I_EDST1;
    int* edst2 = I + I_EDST2;

    float* htar = out + 4LL * NN * HH;   // slot 4 of the output stack

    auto cdiv = [](long long a, long long b) { return (int)((a + b - 1) / b); };

    // CSR build for both relations
    zero_kernel<<<cdiv(NN, 256), 256>>>(deg1, deg2, ctr);
    hist_kernel<<<cdiv(EE, 256), 256>>>(src1, deg1, EE);
    hist_kernel<<<cdiv(EE, 256), 256>>>(src2, deg2, EE);
    base_kernel<<<cdiv(NN, 256), 256>>>(deg1, row1, cur1, ctr + 0, NN);
    base_kernel<<<cdiv(NN, 256), 256>>>(deg2, row2, cur2, ctr + 1, NN);
    reorder_kernel<<<cdiv(EE, 256), 256>>>(src1, dst1, cur1, edst1, EE);
    reorder_kernel<<<cdiv(EE, 256), 256>>>(src2, dst2, cur2, edst2, EE);

    // Input GEMMs (+bias +ELU)
    gemm64_kernel<DIN, true><<<cdiv(NN1, 64), 256>>>(feats1,    W1, b1, hnei1, NN1);
    gemm64_kernel<DIN, true><<<cdiv(NN2, 64), 256>>>(feats2,    W2, b2, hnei2, NN2);
    gemm64_kernel<DIN, true><<<cdiv(NN,  64), 256>>>(feats0,    W0, b0, htar,  NN);
    gemm64_kernel<DIN, true><<<cdiv(NN,  64), 256>>>(mask_feat, W0, b0, hmask, NN);

    // Gather-aggregate (writes sum exactly once per row; deg doubles as cnt)
    agg_kernel<<<cdiv((long long)NN * 32, 256), 256>>>(row1, deg1, edst1,
                                                       (const float2*)hnei1, (float2*)sum1, NN);
    agg_kernel<<<cdiv((long long)NN * 32, 256), 256>>>(row2, deg2, edst2,
                                                       (const float2*)hnei2, (float2*)sum2, NN);

    // T_r = sum_r @ A_r (divide by deg deferred to final — commutes with matmul)
    gemm64_kernel<HH, false><<<cdiv(NN, 64), 256>>>(sum1, A0, nullptr, T1, NN);
    gemm64_kernel<HH, false><<<cdiv(NN, 64), 256>>>(sum2, A1, nullptr, T2, NN);

    // Fused epilogue
    final_kernel<<<cdiv((long long)NN * 16, 256), 256>>>((const float4*)T1, (const float4*)T2,
                                                         deg1, deg2, (const float4*)hmask, out);
}